// round 15
// baseline (speedup 1.0000x reference)
#include <cuda_runtime.h>
#include <cstdint>

typedef unsigned long long u64;

#define T_STEPS 480000
#define PF 2
#define CTAS_PER_SM 9
#define NBLOCKS (148 * CTAS_PER_SM)          // 1332, single wave at 9 CTAs/SM
#define CHUNK_L 361                          // 1332*361 >= 480000
#define WARMUP  32

// Per-step packed params (padded past T):
//   A = {K, R01, R11, R10},  B = {R12*v, R02*v, dr, 0},  K = R00 + R01*R10_prev
__device__ float g_params[(T_STEPS + 8) * 8];
__device__ float g_sink;                     // branch-free overshoot target

// ---------------------------------------------------------------------------
// Parallel precompute of all carry-independent WDF coefficients.
// ---------------------------------------------------------------------------
__global__ void ndc_precompute(const float* __restrict__ v_in,
                               const float* __restrict__ vs_r,
                               const float* __restrict__ fs) {
    int t = blockIdx.x * blockDim.x + threadIdx.x;
    if (t >= T_STEPS + 8) return;
    float4 A, B;
    if (t >= T_STEPS) {
        A = make_float4(0.f, 0.f, 0.f, 0.f);
        B = A;
    } else {
        const float C1 = 4.7e-9f;
        float f   = fs[t];
        float vr  = vs_r[t];
        float c1r = 1.0f / (2.0f * C1 * f);
        float r0  = c1r * vr / (c1r + vr);
        float g0  = 1.0f / r0, g1 = 1.0f / c1r, g2 = 1.0f / vr;
        float s   = g0 + g1 + g2;
        float P0  = 2.0f * g0 / s, P1 = 2.0f * g1 / s, P2 = 2.0f * g2 / s;
        float R00 = P0 - 1.0f, R01 = P1, R02 = P2;
        float R10 = P0, R11 = P1 - 1.0f, R12 = P2;
        float R10p = 0.0f;
        if (t > 0) {
            float fp = fs[t - 1], vp = vs_r[t - 1];
            float c1p = 1.0f / (2.0f * C1 * fp);
            float rp  = c1p * vp / (c1p + vp);
            float h0 = 1.0f / rp, h1 = 1.0f / c1p, h2 = 1.0f / vp;
            float sp = h0 + h1 + h2;
            R10p = 2.0f * h0 / sp;
        }
        float v = v_in[t];
        float K = fmaf(R01, R10p, R00);
        A = make_float4(K, R01, R11, R10);
        B = make_float4(R12 * v, R02 * v, r0 / 3000.0f, 0.0f);
    }
    float4* p = reinterpret_cast<float4*>(g_params);
    p[2 * t]     = A;
    p[2 * t + 1] = B;
}

// ---------------------------------------------------------------------------
// Packed f32x2 helpers (Blackwell FFMA2 path)
// ---------------------------------------------------------------------------
__device__ __forceinline__ u64 ffma2(u64 a, u64 b, u64 c) {
    u64 d;
    asm("fma.rn.f32x2 %0, %1, %2, %3;" : "=l"(d) : "l"(a), "l"(b), "l"(c));
    return d;
}
__device__ __forceinline__ u64 fadd2(u64 a, u64 b) {
    u64 d;
    asm("add.rn.f32x2 %0, %1, %2;" : "=l"(d) : "l"(a), "l"(b));
    return d;
}
__device__ __forceinline__ float hsum2(u64 a) {
    return __uint_as_float((unsigned)a) + __uint_as_float((unsigned)(a >> 32));
}
__device__ __forceinline__ u64 pack2(float lo, float hi) {
    u64 d;
    asm("mov.b64 %0, {%1, %2};" : "=l"(d) : "f"(lo), "f"(hi));
    return d;
}
__device__ __forceinline__ u64 relu2(u64 x) {
    float lo, hi;
    asm("mov.b64 {%0, %1}, %2;" : "=f"(lo), "=f"(hi) : "l"(x));
    return pack2(fmaxf(lo, 0.0f), fmaxf(hi, 0.0f));
}

// 32x32 matvec with h in SMEM (broadcast reads). Bias in accumulator init.
__device__ __forceinline__ float layer32(const float* sh, const u64* w, float bias) {
    const ulonglong2* h = reinterpret_cast<const ulonglong2*>(sh);
    u64 a0 = (u64)__float_as_uint(bias);
    u64 a1 = 0ull, a2 = 0ull, a3 = 0ull, a4 = 0ull, a5 = 0ull, a6 = 0ull, a7 = 0ull;
    ulonglong2 x0 = h[0], x1 = h[1], x2 = h[2], x3 = h[3];
    a0 = ffma2(w[0], x0.x, a0);
    a1 = ffma2(w[1], x0.y, a1);
    a2 = ffma2(w[2], x1.x, a2);
    a3 = ffma2(w[3], x1.y, a3);
    a4 = ffma2(w[4], x2.x, a4);
    a5 = ffma2(w[5], x2.y, a5);
    a6 = ffma2(w[6], x3.x, a6);
    a7 = ffma2(w[7], x3.y, a7);
    ulonglong2 x4 = h[4], x5 = h[5], x6 = h[6], x7 = h[7];
    a0 = ffma2(w[8],  x4.x, a0);
    a1 = ffma2(w[9],  x4.y, a1);
    a2 = ffma2(w[10], x5.x, a2);
    a3 = ffma2(w[11], x5.y, a3);
    a4 = ffma2(w[12], x6.x, a4);
    a5 = ffma2(w[13], x6.y, a5);
    a6 = ffma2(w[14], x7.x, a6);
    a7 = ffma2(w[15], x7.y, a7);
    u64 b0 = fadd2(a0, a1), b1 = fadd2(a2, a3), b2 = fadd2(a4, a5), b3 = fadd2(a6, a7);
    return hsum2(fadd2(fadd2(b0, b1), fadd2(b2, b3)));
}

// 32x32 matvec with h in registers (fat-lane form, no SMEM).
__device__ __forceinline__ float layer32_reg(const u64* h, const u64* w, float bias) {
    u64 a0 = (u64)__float_as_uint(bias);
    u64 a1 = 0ull, a2 = 0ull, a3 = 0ull, a4 = 0ull, a5 = 0ull, a6 = 0ull, a7 = 0ull;
    a0 = ffma2(w[0], h[0], a0);
    a1 = ffma2(w[1], h[1], a1);
    a2 = ffma2(w[2], h[2], a2);
    a3 = ffma2(w[3], h[3], a3);
    a4 = ffma2(w[4], h[4], a4);
    a5 = ffma2(w[5], h[5], a5);
    a6 = ffma2(w[6], h[6], a6);
    a7 = ffma2(w[7], h[7], a7);
    a0 = ffma2(w[8],  h[8],  a0);
    a1 = ffma2(w[9],  h[9],  a1);
    a2 = ffma2(w[10], h[10], a2);
    a3 = ffma2(w[11], h[11], a3);
    a4 = ffma2(w[12], h[12], a4);
    a5 = ffma2(w[13], h[13], a5);
    a6 = ffma2(w[14], h[14], a6);
    a7 = ffma2(w[15], h[15], a7);
    u64 b0 = fadd2(a0, a1), b1 = fadd2(a2, a3), b2 = fadd2(a4, a5), b3 = fadd2(a6, a7);
    return hsum2(fadd2(fadd2(b0, b1), fadd2(b2, b3)));
}

// Butterfly reduce: bit-identical result in all 32 lanes.
__device__ __forceinline__ float warp_sum32(float p) {
    p += __shfl_xor_sync(0xffffffffu, p, 16);
    p += __shfl_xor_sync(0xffffffffu, p, 8);
    p += __shfl_xor_sync(0xffffffffu, p, 4);
    p += __shfl_xor_sync(0xffffffffu, p, 2);
    p += __shfl_xor_sync(0xffffffffu, p, 1);
    return p;
}

// ---------------------------------------------------------------------------
// Overlap-chunk parallel scan, fat-lane input layer: every lane computes the
// FULL 32-vector input activation in registers (it depends only on the scalar
// dpa plus per-unit constants), eliminating the first SMEM broadcast round.
// One SMEM round (hidden1 -> hidden2) + shuffle reduce remain.
// ---------------------------------------------------------------------------
__global__ void __launch_bounds__(32, CTAS_PER_SM) ndc_scan(
    const float* __restrict__ W_in, const float* __restrict__ b_in,
    const float* __restrict__ W_h,  const float* __restrict__ b_h,
    const float* __restrict__ W_out, const float* __restrict__ b_out,
    float* __restrict__ out)
{
    __shared__ __align__(16) float sh[32];
    const int lane = threadIdx.x;

    const int cstart = blockIdx.x * CHUNK_L;
    if (cstart >= T_STEPS) return;
    int cend = cstart + CHUNK_L;
    if (cend > T_STEPS) cend = T_STEPS;
    int t0 = cstart - WARMUP;
    if (t0 < 0) t0 = 0;

    // Full W_in vectors per lane (fat-lane input layer), packed f32x2 by j-pair
    u64 win0p[16], win1p[16], binp[16];
    {
        const float4* wi = reinterpret_cast<const float4*>(W_in);  // {w0_j, w1_j, w0_j+1, w1_j+1}
        const float2* bi = reinterpret_cast<const float2*>(b_in);
#pragma unroll
        for (int k = 0; k < 16; ++k) {
            float4 q = wi[k];
            win0p[k] = pack2(q.x, q.z);
            win1p[k] = pack2(q.y, q.w);
            float2 b = bi[k];
            binp[k]  = pack2(b.x, b.y);
        }
    }

    // Per-lane row weights + biases
    float bh1  = b_h[lane];
    float bh2  = b_h[32 + lane];
    float wout = W_out[lane];
    float bout = b_out[0];

    u64 w1[16], w2[16];
    {
        const ulonglong2* r1 = reinterpret_cast<const ulonglong2*>(W_h + lane * 32);
        const ulonglong2* r2 = reinterpret_cast<const ulonglong2*>(W_h + 1024 + lane * 32);
#pragma unroll
        for (int k = 0; k < 8; ++k) {
            ulonglong2 x = r1[k]; w1[2 * k] = x.x; w1[2 * k + 1] = x.y;
            ulonglong2 y = r2[k]; w2[2 * k] = y.x; w2[2 * k + 1] = y.y;
        }
    }

    const float4* Pp = reinterpret_cast<const float4*>(g_params);
    float4 bufA[PF], bufB[PF];
#pragma unroll
    for (int k = 0; k < PF; ++k) {
        bufA[k] = Pp[2 * (t0 + k)];
        bufB[k] = Pp[2 * (t0 + k) + 1];
    }

    // Recurrence state: zeros wash out over WARMUP steps (exact for chunk 0).
    float dpb    = 0.0f;
    float b1tail = 0.0f;
    float R10p   = (t0 > 0) ? Pp[2 * (t0 - 1)].w : 0.0f;

    // Prepared (one step ahead): Kc, uc for step t0 (b1tail_{t0-1} = 0)
    float Kc = bufA[0].x;
    float uc = bufB[0].y;

    for (int t = t0; t < cend; t += PF) {
#pragma unroll
        for (int u = 0; u < PF; ++u) {
            float4 A = bufA[u];
            float4 B = bufB[u];
            int nu = (u + 1) & (PF - 1);
            float4 nA = bufA[nu];
            float4 nB = bufB[nu];

            // ---- critical path: dpb -> dpa -> h_all (registers, no smem) ----
            float dpa  = fmaf(Kc, dpb, uc);
            u64 dpa2 = pack2(dpa, dpa);
            u64 dr2  = pack2(B.z, B.z);
            u64 hreg[16];
#pragma unroll
            for (int k = 0; k < 16; ++k) {
                u64 c2 = ffma2(win1p[k], dr2, binp[k]);   // param-only, off-path
                hreg[k] = relu2(ffma2(win0p[k], dpa2, c2));
            }

            // ---- hidden layer 1 from registers ----
            float hh = fmaxf(layer32_reg(hreg, w1, bh1), 0.0f);
            sh[lane] = hh;
            // --- STS-drain shadow: carry glue + next-step prep + prefetch ---
            float hdpa = 0.5f * dpa;
            float b1f  = fmaf(R10p, dpb, b1tail);
            b1tail     = fmaf(A.z, b1f, B.x);
            R10p       = A.w;
            uc         = fmaf(nA.y, b1tail, nB.y);
            Kc         = nA.x;
            int tp = t + u + PF;
            bufA[u] = Pp[2 * tp];
            bufB[u] = Pp[2 * tp + 1];
            __syncthreads();

            // ---- hidden layer 2 (smem broadcast) + shuffle reduce ----
            float h3   = fmaxf(layer32(sh, w2, bh2), 0.0f);
            float dpbn = warp_sum32(wout * h3) + bout;

            // Branch-free store (warmup -> out[cstart], overshoot -> sink)
            float oval = fmaf(0.5f, dpbn, hdpa);
            int ta   = t + u;
            int addr = ta > cstart ? ta : cstart;
            float* ptr = (ta < cend) ? (out + addr) : &g_sink;
            *ptr = oval;

            dpb = dpbn;
        }
    }
}

extern "C" void kernel_launch(void* const* d_in, const int* in_sizes, int n_in,
                              void* d_out, int out_size) {
    const float* v_in  = (const float*)d_in[0];
    const float* vs_r  = (const float*)d_in[1];
    const float* fs    = (const float*)d_in[2];
    const float* W_in  = (const float*)d_in[3];
    const float* b_in  = (const float*)d_in[4];
    const float* W_h   = (const float*)d_in[5];
    const float* b_h   = (const float*)d_in[6];
    const float* W_out = (const float*)d_in[7];
    const float* b_out = (const float*)d_in[8];
    float* out = (float*)d_out;

    ndc_precompute<<<(T_STEPS + 8 + 255) / 256, 256>>>(v_in, vs_r, fs);
    ndc_scan<<<NBLOCKS, 32>>>(W_in, b_in, W_h, b_h, W_out, b_out, out);
}

// round 16
// speedup vs baseline: 1.5724x; 1.5724x over previous
#include <cuda_runtime.h>
#include <cstdint>

typedef unsigned long long u64;

#define T_STEPS 480000
#define NSM 152
#define CTAS_PER_SM 12
#define NBLOCKS (NSM * CTAS_PER_SM)       // 1824 CTAs, 2 streams each = 3648 chunks
#define CHUNK_L 132                       // 3648*132 = 481536 >= 480000
#define WARMUP  24                        // lambda < 0.59 proven => residual < 4e-6
#define T_PAD   (3648 * CHUNK_L + 8)      // params padded past max touched index

// Per-step packed params (zero-padded past T):
//   A = {K, R01, R11, R10},  B = {R12*v, R02*v, dr, 0},  K = R00 + R01*R10_prev
__device__ float g_params[T_PAD * 8];
__device__ float g_sink;                  // branch-free overshoot target

// ---------------------------------------------------------------------------
// Parallel precompute of all carry-independent WDF coefficients.
// ---------------------------------------------------------------------------
__global__ void ndc_precompute(const float* __restrict__ v_in,
                               const float* __restrict__ vs_r,
                               const float* __restrict__ fs) {
    int t = blockIdx.x * blockDim.x + threadIdx.x;
    if (t >= T_PAD) return;
    float4 A, B;
    if (t >= T_STEPS) {
        A = make_float4(0.f, 0.f, 0.f, 0.f);
        B = A;
    } else {
        const float C1 = 4.7e-9f;
        float f   = fs[t];
        float vr  = vs_r[t];
        float c1r = 1.0f / (2.0f * C1 * f);
        float r0  = c1r * vr / (c1r + vr);
        float g0  = 1.0f / r0, g1 = 1.0f / c1r, g2 = 1.0f / vr;
        float s   = g0 + g1 + g2;
        float P0  = 2.0f * g0 / s, P1 = 2.0f * g1 / s, P2 = 2.0f * g2 / s;
        float R00 = P0 - 1.0f, R01 = P1, R02 = P2;
        float R10 = P0, R11 = P1 - 1.0f, R12 = P2;
        float R10p = 0.0f;
        if (t > 0) {
            float fp = fs[t - 1], vp = vs_r[t - 1];
            float c1p = 1.0f / (2.0f * C1 * fp);
            float rp  = c1p * vp / (c1p + vp);
            float h0 = 1.0f / rp, h1 = 1.0f / c1p, h2 = 1.0f / vp;
            float sp = h0 + h1 + h2;
            R10p = 2.0f * h0 / sp;
        }
        float v = v_in[t];
        float K = fmaf(R01, R10p, R00);
        A = make_float4(K, R01, R11, R10);
        B = make_float4(R12 * v, R02 * v, r0 / 3000.0f, 0.0f);
    }
    float4* p = reinterpret_cast<float4*>(g_params);
    p[2 * t]     = A;
    p[2 * t + 1] = B;
}

// ---------------------------------------------------------------------------
// Packed f32x2 helpers (Blackwell FFMA2 path)
// ---------------------------------------------------------------------------
__device__ __forceinline__ u64 ffma2(u64 a, u64 b, u64 c) {
    u64 d;
    asm("fma.rn.f32x2 %0, %1, %2, %3;" : "=l"(d) : "l"(a), "l"(b), "l"(c));
    return d;
}
__device__ __forceinline__ u64 fadd2(u64 a, u64 b) {
    u64 d;
    asm("add.rn.f32x2 %0, %1, %2;" : "=l"(d) : "l"(a), "l"(b));
    return d;
}
__device__ __forceinline__ float hsum2(u64 a) {
    return __uint_as_float((unsigned)a) + __uint_as_float((unsigned)(a >> 32));
}

// 32x32 matvec: lane holds one row (16 packed f32x2 weights); h broadcast via
// smem. Bias folded into accumulator init. 8 accumulators -> chain depth 2.
__device__ __forceinline__ float layer32(const float* sh, const u64* w, float bias) {
    const ulonglong2* h = reinterpret_cast<const ulonglong2*>(sh);
    u64 a0 = (u64)__float_as_uint(bias);
    u64 a1 = 0ull, a2 = 0ull, a3 = 0ull, a4 = 0ull, a5 = 0ull, a6 = 0ull, a7 = 0ull;
    ulonglong2 x0 = h[0], x1 = h[1], x2 = h[2], x3 = h[3];
    a0 = ffma2(w[0], x0.x, a0);
    a1 = ffma2(w[1], x0.y, a1);
    a2 = ffma2(w[2], x1.x, a2);
    a3 = ffma2(w[3], x1.y, a3);
    a4 = ffma2(w[4], x2.x, a4);
    a5 = ffma2(w[5], x2.y, a5);
    a6 = ffma2(w[6], x3.x, a6);
    a7 = ffma2(w[7], x3.y, a7);
    ulonglong2 x4 = h[4], x5 = h[5], x6 = h[6], x7 = h[7];
    a0 = ffma2(w[8],  x4.x, a0);
    a1 = ffma2(w[9],  x4.y, a1);
    a2 = ffma2(w[10], x5.x, a2);
    a3 = ffma2(w[11], x5.y, a3);
    a4 = ffma2(w[12], x6.x, a4);
    a5 = ffma2(w[13], x6.y, a5);
    a6 = ffma2(w[14], x7.x, a6);
    a7 = ffma2(w[15], x7.y, a7);
    u64 b0 = fadd2(a0, a1), b1 = fadd2(a2, a3), b2 = fadd2(a4, a5), b3 = fadd2(a6, a7);
    return hsum2(fadd2(fadd2(b0, b1), fadd2(b2, b3)));
}

// Dual interleaved butterfly reduce: the two dependent SHFL chains overlap,
// so the 5x26-cycle latency is paid once, not twice.
__device__ __forceinline__ void warp_sum32_dual(float& p0, float& p1) {
    float q0, q1;
    q0 = __shfl_xor_sync(0xffffffffu, p0, 16); q1 = __shfl_xor_sync(0xffffffffu, p1, 16);
    p0 += q0; p1 += q1;
    q0 = __shfl_xor_sync(0xffffffffu, p0, 8);  q1 = __shfl_xor_sync(0xffffffffu, p1, 8);
    p0 += q0; p1 += q1;
    q0 = __shfl_xor_sync(0xffffffffu, p0, 4);  q1 = __shfl_xor_sync(0xffffffffu, p1, 4);
    p0 += q0; p1 += q1;
    q0 = __shfl_xor_sync(0xffffffffu, p0, 2);  q1 = __shfl_xor_sync(0xffffffffu, p1, 2);
    p0 += q0; p1 += q1;
    q0 = __shfl_xor_sync(0xffffffffu, p0, 1);  q1 = __shfl_xor_sync(0xffffffffu, p1, 1);
    p0 += q0; p1 += q1;
}

// ---------------------------------------------------------------------------
// Overlap-chunk parallel scan, TWO independent chunk-streams per warp.
// Streams share the weight registers; their stall windows (LDS returns,
// shuffle chains) interleave, raising per-warp issue efficiency.
// ---------------------------------------------------------------------------
__global__ void __launch_bounds__(32, CTAS_PER_SM) ndc_scan(
    const float* __restrict__ W_in, const float* __restrict__ b_in,
    const float* __restrict__ W_h,  const float* __restrict__ b_h,
    const float* __restrict__ W_out, const float* __restrict__ b_out,
    float* __restrict__ out)
{
    __shared__ __align__(16) float shA0[32], shA1[32];
    __shared__ __align__(16) float shB0[32], shB1[32];
    const int lane = threadIdx.x;

    // Stream chunk bounds (stream s handles chunk 2*bid + s)
    const int c0s = (blockIdx.x * 2 + 0) * CHUNK_L;
    const int c1s = (blockIdx.x * 2 + 1) * CHUNK_L;
    int c0e = c0s + CHUNK_L; if (c0e > T_STEPS) c0e = T_STEPS;
    int c1e = c1s + CHUNK_L; if (c1e > T_STEPS) c1e = T_STEPS;
    int t00 = c0s - WARMUP; if (t00 < 0) t00 = 0;   // stream0 absolute start
    // Both streams execute the same number of steps, aligned to stream0's count.
    const int nsteps = (c0s + CHUNK_L) - t00;        // chunk0 full span + warmup
    const int t10 = c1s + CHUNK_L - nsteps;          // stream1 start (>= 0 always)

    // Per-lane weights
    float win0 = W_in[2 * lane];
    float win1 = W_in[2 * lane + 1];
    float bin  = b_in[lane];
    float bh1  = b_h[lane];
    float bh2  = b_h[32 + lane];
    float wout = W_out[lane];
    float bout = b_out[0];

    u64 w1[16], w2[16];
    {
        const ulonglong2* r1 = reinterpret_cast<const ulonglong2*>(W_h + lane * 32);
        const ulonglong2* r2 = reinterpret_cast<const ulonglong2*>(W_h + 1024 + lane * 32);
#pragma unroll
        for (int k = 0; k < 8; ++k) {
            ulonglong2 x = r1[k]; w1[2 * k] = x.x; w1[2 * k + 1] = x.y;
            ulonglong2 y = r2[k]; w2[2 * k] = y.x; w2[2 * k + 1] = y.y;
        }
    }

    const float4* Pp = reinterpret_cast<const float4*>(g_params);
    // Current-step params per stream (prefetched one step ahead)
    float4 A0 = Pp[2 * t00],  B0 = Pp[2 * t00 + 1];
    float4 A1 = Pp[2 * t10],  B1 = Pp[2 * t10 + 1];

    // Recurrence state per stream
    float dpb0 = 0.0f, b1t0 = 0.0f, R10p0 = (t00 > 0) ? Pp[2 * (t00 - 1)].w : 0.0f;
    float dpb1 = 0.0f, b1t1 = 0.0f, R10p1 = Pp[2 * (t10 - 1)].w;

    // Prepared one-step-ahead values
    float Kc0 = A0.x, uc0 = B0.y;
    float Kc1 = A1.x, uc1 = B1.y;
    float g0 = fmaf(win0, uc0, fmaf(win1, B0.z, bin));
    float g1 = fmaf(win0, uc1, fmaf(win1, B1.z, bin));
    float wK0 = win0 * Kc0, wK1 = win0 * Kc1;

    for (int s = 0; s < nsteps; ++s) {
        const int ta0 = t00 + s;
        const int ta1 = t10 + s;

        // ---- round 1: input layers (both streams) ----
        float h0 = fmaxf(fmaf(wK0, dpb0, g0), 0.0f);
        float h1 = fmaxf(fmaf(wK1, dpb1, g1), 0.0f);
        shA0[lane] = h0;
        shA1[lane] = h1;
        // STS-drain shadow: glue + next-step prep + prefetch, both streams
        float dpa0 = fmaf(Kc0, dpb0, uc0);
        float dpa1 = fmaf(Kc1, dpb1, uc1);
        float hd0  = 0.5f * dpa0;
        float hd1  = 0.5f * dpa1;
        float f0   = fmaf(R10p0, dpb0, b1t0);
        float f1   = fmaf(R10p1, dpb1, b1t1);
        b1t0 = fmaf(A0.z, f0, B0.x);
        b1t1 = fmaf(A1.z, f1, B1.x);
        R10p0 = A0.w; R10p1 = A1.w;
        float4 nA0 = Pp[2 * (ta0 + 1)], nB0 = Pp[2 * (ta0 + 1) + 1];
        float4 nA1 = Pp[2 * (ta1 + 1)], nB1 = Pp[2 * (ta1 + 1) + 1];
        uc0 = fmaf(nA0.y, b1t0, nB0.y);
        uc1 = fmaf(nA1.y, b1t1, nB1.y);
        Kc0 = nA0.x; Kc1 = nA1.x;
        g0  = fmaf(win0, uc0, fmaf(win1, nB0.z, bin));
        g1  = fmaf(win0, uc1, fmaf(win1, nB1.z, bin));
        wK0 = win0 * Kc0; wK1 = win0 * Kc1;
        A0 = nA0; B0 = nB0; A1 = nA1; B1 = nB1;
        __syncthreads();

        // ---- round 2: hidden layer 1 (both streams, interleaved issue) ----
        float hh0 = fmaxf(layer32(shA0, w1, bh1), 0.0f);
        float hh1 = fmaxf(layer32(shA1, w1, bh1), 0.0f);
        shB0[lane] = hh0;
        shB1[lane] = hh1;
        __syncthreads();

        // ---- round 3: hidden layer 2 + dual shuffle reduce ----
        float p0 = wout * fmaxf(layer32(shB0, w2, bh2), 0.0f);
        float p1 = wout * fmaxf(layer32(shB1, w2, bh2), 0.0f);
        warp_sum32_dual(p0, p1);
        float n0 = p0 + bout;
        float n1 = p1 + bout;

        // Branch-free stores (warmup -> out[cstart], overshoot -> sink)
        float o0 = fmaf(0.5f, n0, hd0);
        float o1 = fmaf(0.5f, n1, hd1);
        int a0 = ta0 > c0s ? ta0 : c0s;
        int a1 = ta1 > c1s ? ta1 : c1s;
        float* q0 = (ta0 < c0e && c0s < T_STEPS) ? (out + a0) : &g_sink;
        float* q1 = (ta1 < c1e && c1s < T_STEPS) ? (out + a1) : &g_sink;
        *q0 = o0;
        *q1 = o1;

        dpb0 = n0;
        dpb1 = n1;
    }
}

extern "C" void kernel_launch(void* const* d_in, const int* in_sizes, int n_in,
                              void* d_out, int out_size) {
    const float* v_in  = (const float*)d_in[0];
    const float* vs_r  = (const float*)d_in[1];
    const float* fs    = (const float*)d_in[2];
    const float* W_in  = (const float*)d_in[3];
    const float* b_in  = (const float*)d_in[4];
    const float* W_h   = (const float*)d_in[5];
    const float* b_h   = (const float*)d_in[6];
    const float* W_out = (const float*)d_in[7];
    const float* b_out = (const float*)d_in[8];
    float* out = (float*)d_out;

    ndc_precompute<<<(T_PAD + 255) / 256, 256>>>(v_in, vs_r, fs);
    ndc_scan<<<NBLOCKS, 32>>>(W_in, b_in, W_h, b_h, W_out, b_out, out);
}